// round 3
// baseline (speedup 1.0000x reference)
#include <cuda_runtime.h>
#include <math.h>
#include <stdint.h>

#define NNODES 100000
#define NEDGES 3200000
#define NF 512
#define NH 256
#define NCLS 40
#define NLAY 8
#define NB 9            // ortho batches: W0 + 8 layer weights
#define EPSV 1e-5f
#define ALPHA 0.1f

// ---------------- device scratch (no runtime allocation allowed) ----------------
__device__ float g_h[(size_t)NNODES * NH];
__device__ float g_h0[(size_t)NNODES * NH];
__device__ float g_sup[(size_t)NNODES * NH];
__device__ float g_Zc0[NH * NF];
__device__ float g_ZcL[NLAY * NH * NH];
__device__ float g_S[NB * NH * NH];
__device__ float g_Bmat[NB * NH * NH];
__device__ float g_B2[NB * NH * NH];
__device__ float g_B3[NB * NH * NH];
__device__ float g_nrm[NB];
__device__ float g_W0o[NH * NF];
__device__ float g_W0T[NF * NH];
__device__ float g_tW[NLAY * NH * NH];
__device__ int   g_cnt[NNODES];
__device__ int   g_excl[NNODES];
__device__ int   g_bsum[128];
__device__ int   g_rowptr[NNODES + 1];
__device__ int   g_cursor[NNODES];
__device__ int   g_col[NEDGES];
__device__ float g_wt[NEDGES];

// ---------------- helpers ----------------
__device__ __forceinline__ float blk_reduce256(float v, float* red) {
    int t = threadIdx.x;
    red[t] = v; __syncthreads();
    for (int o = 128; o > 0; o >>= 1) {
        if (t < o) red[t] += red[t + o];
        __syncthreads();
    }
    return red[0];
}

// ---------------- weight preprocessing ----------------
// Center rows of W0 -> Zc0 (k = NF)
__global__ void k_center0(const float* __restrict__ W0) {
    __shared__ float red[256];
    int r = blockIdx.x;
    float s = 0.f;
    for (int c = threadIdx.x; c < NF; c += 256) s += W0[r * NF + c];
    float mean = blk_reduce256(s, red) / (float)NF;
    for (int c = threadIdx.x; c < NF; c += 256)
        g_Zc0[r * NF + c] = W0[r * NF + c] - mean;
}

// we = 0.5*convW[l] + 0.5*I, then center rows -> ZcL (k = NH)
__global__ void k_centerL(const float* __restrict__ convW) {
    __shared__ float red[256];
    int g = blockIdx.x;           // l*NH + r
    int l = g / NH, r = g % NH;
    int c = threadIdx.x;          // 256 threads == NH
    float v = 0.5f * convW[(size_t)l * NH * NH + r * NH + c] + (c == r ? 0.5f : 0.f);
    float mean = blk_reduce256(v, red) / (float)NH;
    g_ZcL[(size_t)l * NH * NH + r * NH + c] = v - mean;
}

// Batched covariance: S = Zc @ Zc^T + eps*I.  64x64 tile, 4x4/thread, NT layout.
__global__ void __launch_bounds__(256) k_cov() {
    const int z = blockIdx.z;
    const int K = (z == 0) ? NF : NH;
    const float* A = (z == 0) ? g_Zc0 : (g_ZcL + (size_t)(z - 1) * NH * NH);
    float* C = g_S + (size_t)z * NH * NH;
    __shared__ float As[16][64];
    __shared__ float Bs[16][64];
    const int bi = blockIdx.x * 64, bj = blockIdx.y * 64;
    const int tid = threadIdx.x, tx = tid & 15, ty = tid >> 4;
    float acc[4][4] = {};
    for (int k0 = 0; k0 < K; k0 += 16) {
        int r = tid >> 2, kq = (tid & 3) << 2;
        float4 va = *(const float4*)(A + (size_t)(bi + r) * K + k0 + kq);
        As[kq][r] = va.x; As[kq + 1][r] = va.y; As[kq + 2][r] = va.z; As[kq + 3][r] = va.w;
        float4 vb = *(const float4*)(A + (size_t)(bj + r) * K + k0 + kq);
        Bs[kq][r] = vb.x; Bs[kq + 1][r] = vb.y; Bs[kq + 2][r] = vb.z; Bs[kq + 3][r] = vb.w;
        __syncthreads();
#pragma unroll
        for (int k = 0; k < 16; k++) {
            float a[4], b[4];
#pragma unroll
            for (int i = 0; i < 4; i++) a[i] = As[k][ty * 4 + i];
#pragma unroll
            for (int j = 0; j < 4; j++) b[j] = Bs[k][tx * 4 + j];
#pragma unroll
            for (int i = 0; i < 4; i++)
#pragma unroll
                for (int j = 0; j < 4; j++) acc[i][j] = fmaf(a[i], b[j], acc[i][j]);
        }
        __syncthreads();
    }
#pragma unroll
    for (int i = 0; i < 4; i++)
#pragma unroll
        for (int j = 0; j < 4; j++) {
            int gi = bi + ty * 4 + i, gj = bj + tx * 4 + j;
            float v = acc[i][j];
            if (gi == gj) v += EPSV;
            C[(size_t)gi * NH + gj] = v;
        }
}

// Frobenius norm per batch
__global__ void k_norm() {
    __shared__ float red[256];
    const int z = blockIdx.x;
    const float* S = g_S + (size_t)z * NH * NH;
    float s = 0.f;
    for (int i = threadIdx.x; i < NH * NH; i += 256) { float v = S[i]; s += v * v; }
    float tot = blk_reduce256(s, red);
    if (threadIdx.x == 0) g_nrm[z] = sqrtf(tot);
}

// S /= norm ; B = I
__global__ void k_scaleinit() {
    int idx = blockIdx.x * 256 + threadIdx.x;      // < NB*65536
    int z = idx >> 16;
    int i = (idx >> 8) & 255, j = idx & 255;
    float inv = 1.f / g_nrm[z];
    g_S[idx] *= inv;
    g_Bmat[idx] = (i == j) ? 1.f : 0.f;
}

// Batched 256x256x256 NN GEMM.  MODE 0: C = A@B ;  MODE 1: C = 1.5*C - 0.5*(A@B)
template <int MODE>
__global__ void __launch_bounds__(256) k_ns(const float* __restrict__ Ab,
                                            const float* __restrict__ Bb,
                                            float* __restrict__ Cb) {
    const int z = blockIdx.z;
    const float* A = Ab + (size_t)z * NH * NH;
    const float* B = Bb + (size_t)z * NH * NH;
    float* C = Cb + (size_t)z * NH * NH;
    __shared__ float As[16][64];
    __shared__ float Bs[16][64];
    const int bi = blockIdx.x * 64, bj = blockIdx.y * 64;
    const int tid = threadIdx.x, tx = tid & 15, ty = tid >> 4;
    float acc[4][4] = {};
    for (int k0 = 0; k0 < NH; k0 += 16) {
        { int r = tid >> 2, kq = (tid & 3) << 2;
          float4 v = *(const float4*)(A + (size_t)(bi + r) * NH + k0 + kq);
          As[kq][r] = v.x; As[kq + 1][r] = v.y; As[kq + 2][r] = v.z; As[kq + 3][r] = v.w; }
        { int kr = tid >> 4, nc = (tid & 15) << 2;
          *(float4*)&Bs[kr][nc] = *(const float4*)(B + (size_t)(k0 + kr) * NH + bj + nc); }
        __syncthreads();
#pragma unroll
        for (int k = 0; k < 16; k++) {
            float a[4], b[4];
#pragma unroll
            for (int i = 0; i < 4; i++) a[i] = As[k][ty * 4 + i];
#pragma unroll
            for (int j = 0; j < 4; j++) b[j] = Bs[k][tx * 4 + j];
#pragma unroll
            for (int i = 0; i < 4; i++)
#pragma unroll
                for (int j = 0; j < 4; j++) acc[i][j] = fmaf(a[i], b[j], acc[i][j]);
        }
        __syncthreads();
    }
#pragma unroll
    for (int i = 0; i < 4; i++)
#pragma unroll
        for (int j = 0; j < 4; j++) {
            int gi = bi + ty * 4 + i, gj = bj + tx * 4 + j;
            size_t off = (size_t)gi * NH + gj;
            if (MODE == 0) C[off] = acc[i][j];
            else           C[off] = 1.5f * C[off] - 0.5f * acc[i][j];
        }
}

// W_out = (B_t @ Zc) * rsqrt(norm).  z=0 -> W0o (N=512), else tW[l] (N=256)
__global__ void __launch_bounds__(256) k_wfinal() {
    const int z = blockIdx.z;
    const int Nz = (z == 0) ? NF : NH;
    if (blockIdx.y * 64 >= Nz) return;
    const float* A = g_Bmat + (size_t)z * NH * NH;
    const float* B = (z == 0) ? g_Zc0 : (g_ZcL + (size_t)(z - 1) * NH * NH);
    float* C = (z == 0) ? g_W0o : (g_tW + (size_t)(z - 1) * NH * NH);
    __shared__ float As[16][64];
    __shared__ float Bs[16][64];
    const int bi = blockIdx.x * 64, bj = blockIdx.y * 64;
    const int tid = threadIdx.x, tx = tid & 15, ty = tid >> 4;
    float acc[4][4] = {};
    for (int k0 = 0; k0 < NH; k0 += 16) {
        { int r = tid >> 2, kq = (tid & 3) << 2;
          float4 v = *(const float4*)(A + (size_t)(bi + r) * NH + k0 + kq);
          As[kq][r] = v.x; As[kq + 1][r] = v.y; As[kq + 2][r] = v.z; As[kq + 3][r] = v.w; }
        { int kr = tid >> 4, nc = (tid & 15) << 2;
          *(float4*)&Bs[kr][nc] = *(const float4*)(B + (size_t)(k0 + kr) * Nz + bj + nc); }
        __syncthreads();
#pragma unroll
        for (int k = 0; k < 16; k++) {
            float a[4], b[4];
#pragma unroll
            for (int i = 0; i < 4; i++) a[i] = As[k][ty * 4 + i];
#pragma unroll
            for (int j = 0; j < 4; j++) b[j] = Bs[k][tx * 4 + j];
#pragma unroll
            for (int i = 0; i < 4; i++)
#pragma unroll
                for (int j = 0; j < 4; j++) acc[i][j] = fmaf(a[i], b[j], acc[i][j]);
        }
        __syncthreads();
    }
    float sc = rsqrtf(g_nrm[z]);
#pragma unroll
    for (int i = 0; i < 4; i++)
#pragma unroll
        for (int j = 0; j < 4; j++) {
            int gi = bi + ty * 4 + i, gj = bj + tx * 4 + j;
            C[(size_t)gi * Nz + gj] = acc[i][j] * sc;
        }
}

__global__ void k_transpose() {
    int idx = blockIdx.x * 256 + threadIdx.x;   // < NF*NH
    int k = idx >> 8, n = idx & 255;
    g_W0T[idx] = g_W0o[(size_t)n * NF + k];
}

// ---------------- big fused GEMM (N = 256 fixed) ----------------
// mode 0: C = relu(A@B + bias), C2 = C          (input projection, makes h and h0)
// mode 1: C = relu(theta*(A@B) + (1-theta)*R)   (layer transform)
__global__ void __launch_bounds__(256) k_gemm_big(
    const float* __restrict__ A, const float* __restrict__ B,
    float* __restrict__ C, float* __restrict__ C2,
    const float* __restrict__ bias, const float* __restrict__ R,
    int M, int K, float theta, int mode) {
    __shared__ float As[16][128];
    __shared__ float Bs[16][128];
    const int bm = blockIdx.x * 128;
    const int bn = blockIdx.y * 128;
    const int tid = threadIdx.x, tx = tid & 15, ty = tid >> 4;
    float acc[8][8];
#pragma unroll
    for (int i = 0; i < 8; i++)
#pragma unroll
        for (int j = 0; j < 8; j++) acc[i][j] = 0.f;

    for (int k0 = 0; k0 < K; k0 += 16) {
#pragma unroll
        for (int i = 0; i < 2; i++) {
            int q = tid + i * 256;
            int r = q >> 2, kq = (q & 3) << 2;
            int gm = bm + r;
            float4 v = make_float4(0.f, 0.f, 0.f, 0.f);
            if (gm < M) v = *(const float4*)(A + (size_t)gm * K + k0 + kq);
            As[kq][r] = v.x; As[kq + 1][r] = v.y; As[kq + 2][r] = v.z; As[kq + 3][r] = v.w;
        }
#pragma unroll
        for (int i = 0; i < 2; i++) {
            int q = tid + i * 256;
            int kr = q >> 5, nc = (q & 31) << 2;
            *(float4*)&Bs[kr][nc] = *(const float4*)(B + (size_t)(k0 + kr) * NH + bn + nc);
        }
        __syncthreads();
#pragma unroll
        for (int k = 0; k < 16; k++) {
            float a[8], b[8];
#pragma unroll
            for (int i = 0; i < 8; i++) a[i] = As[k][ty * 8 + i];
#pragma unroll
            for (int j = 0; j < 8; j++) b[j] = Bs[k][tx * 8 + j];
#pragma unroll
            for (int i = 0; i < 8; i++)
#pragma unroll
                for (int j = 0; j < 8; j++) acc[i][j] = fmaf(a[i], b[j], acc[i][j]);
        }
        __syncthreads();
    }
#pragma unroll
    for (int i = 0; i < 8; i++) {
        int gm = bm + ty * 8 + i;
        if (gm < M) {
#pragma unroll
            for (int j = 0; j < 8; j++) {
                int gn = bn + tx * 8 + j;
                size_t off = (size_t)gm * NH + gn;
                if (mode == 0) {
                    float v = acc[i][j] + bias[gn];
                    v = v > 0.f ? v : 0.f;
                    C[off] = v;
                    C2[off] = v;
                } else {
                    float r = R[off];
                    float v = theta * acc[i][j] + (1.f - theta) * r;
                    v = v > 0.f ? v : 0.f;
                    C[off] = v;
                }
            }
        }
    }
}

// ---------------- CSR build ----------------
__global__ void k_zero() {
    int i = blockIdx.x * 256 + threadIdx.x;
    if (i < NNODES) g_cnt[i] = 0;
}
__global__ void k_hist(const int* __restrict__ edst) {
    int i = blockIdx.x * 256 + threadIdx.x;
    if (i < NEDGES) atomicAdd(&g_cnt[edst[i]], 1);
}
__global__ void k_scan1() {
    __shared__ int s[1024];
    int i = blockIdx.x * 1024 + threadIdx.x;
    int v = (i < NNODES) ? g_cnt[i] : 0;
    s[threadIdx.x] = v;
    __syncthreads();
    for (int off = 1; off < 1024; off <<= 1) {
        int t = 0;
        if (threadIdx.x >= off) t = s[threadIdx.x - off];
        __syncthreads();
        if (threadIdx.x >= off) s[threadIdx.x] += t;
        __syncthreads();
    }
    if (i < NNODES) g_excl[i] = s[threadIdx.x] - v;
    if (threadIdx.x == 1023) g_bsum[blockIdx.x] = s[1023];
}
__global__ void k_scan2(int nb) {
    if (threadIdx.x == 0) {
        int run = 0;
        for (int i = 0; i < nb; i++) { int t = g_bsum[i]; g_bsum[i] = run; run += t; }
    }
}
__global__ void k_scan3() {
    int i = blockIdx.x * 1024 + threadIdx.x;
    if (i < NNODES) {
        int v = g_excl[i] + g_bsum[i >> 10];
        g_rowptr[i] = v;
        g_cursor[i] = v;
    }
    if (i == 0) g_rowptr[NNODES] = NEDGES;
}
__global__ void k_scatter(const int* __restrict__ esrc, const int* __restrict__ edst,
                          const float* __restrict__ ew) {
    int i = blockIdx.x * 256 + threadIdx.x;
    if (i < NEDGES) {
        int d = edst[i];
        int pos = atomicAdd(&g_cursor[d], 1);
        g_col[pos] = esrc[i];
        g_wt[pos]  = ew[i];
    }
}

// ---------------- SpMM + support fusion ----------------
// sup[node] = 0.9 * sum_e w_e * h[src_e] + 0.1 * h0[node]
__global__ void __launch_bounds__(256) k_spmm() {
    const int node = blockIdx.x * 4 + (threadIdx.x >> 6);
    const int lane = threadIdx.x & 63;
    const int rs = g_rowptr[node];
    const int re = g_rowptr[node + 1];
    float ax = 0.f, ay = 0.f, az = 0.f, aw = 0.f;
    int p = rs;
    for (; p + 2 <= re; p += 2) {
        int s0 = __ldg(&g_col[p]);
        int s1 = __ldg(&g_col[p + 1]);
        float w0 = __ldg(&g_wt[p]);
        float w1 = __ldg(&g_wt[p + 1]);
        float4 v0 = __ldg((const float4*)(g_h + (size_t)s0 * NH) + lane);
        float4 v1 = __ldg((const float4*)(g_h + (size_t)s1 * NH) + lane);
        ax = fmaf(w0, v0.x, ax); ay = fmaf(w0, v0.y, ay);
        az = fmaf(w0, v0.z, az); aw = fmaf(w0, v0.w, aw);
        ax = fmaf(w1, v1.x, ax); ay = fmaf(w1, v1.y, ay);
        az = fmaf(w1, v1.z, az); aw = fmaf(w1, v1.w, aw);
    }
    if (p < re) {
        int s0 = __ldg(&g_col[p]);
        float w0 = __ldg(&g_wt[p]);
        float4 v0 = __ldg((const float4*)(g_h + (size_t)s0 * NH) + lane);
        ax = fmaf(w0, v0.x, ax); ay = fmaf(w0, v0.y, ay);
        az = fmaf(w0, v0.z, az); aw = fmaf(w0, v0.w, aw);
    }
    float4 r = __ldg((const float4*)(g_h0 + (size_t)node * NH) + lane);
    float4 o;
    o.x = 0.9f * ax + ALPHA * r.x;
    o.y = 0.9f * ay + ALPHA * r.y;
    o.z = 0.9f * az + ALPHA * r.z;
    o.w = 0.9f * aw + ALPHA * r.w;
    *((float4*)(g_sup + (size_t)node * NH) + lane) = o;
}

// ---------------- classifier + log_softmax ----------------
// block: 320 threads = 8 nodes x 40 classes
__global__ void __launch_bounds__(320) k_classifier(const float* __restrict__ W1,
                                                    const float* __restrict__ b1,
                                                    float* __restrict__ out) {
    __shared__ float W1s[NCLS * 257];
    __shared__ float logits[8][41];
    __shared__ float mx[8], lse[8];
    const int tid = threadIdx.x;
    for (int idx = tid; idx < NCLS * NH; idx += 320) {
        int c = idx >> 8, k = idx & 255;
        W1s[c * 257 + k] = W1[idx];
    }
    __syncthreads();
    const int ln = tid / NCLS;       // 0..7
    const int c  = tid % NCLS;       // 0..39
    const int node = blockIdx.x * 8 + ln;
    const float* hrow = g_h + (size_t)node * NH;
    float acc = __ldg(&b1[c]);
#pragma unroll 4
    for (int k = 0; k < NH; k++)
        acc = fmaf(__ldg(hrow + k), W1s[c * 257 + k], acc);
    logits[ln][c] = acc;
    __syncthreads();
    if (tid < 8) {
        float m = -1e30f;
        for (int j = 0; j < NCLS; j++) m = fmaxf(m, logits[tid][j]);
        float s = 0.f;
        for (int j = 0; j < NCLS; j++) s += expf(logits[tid][j] - m);
        mx[tid] = m;
        lse[tid] = logf(s);
    }
    __syncthreads();
    out[(size_t)node * NCLS + c] = logits[ln][c] - mx[ln] - lse[ln];
}

// ---------------- launch ----------------
extern "C" void kernel_launch(void* const* d_in, const int* in_sizes, int n_in,
                              void* d_out, int out_size) {
    const float* x     = (const float*)d_in[0];
    const int*   esrc  = (const int*)d_in[1];
    const int*   edst  = (const int*)d_in[2];
    const float* ew    = (const float*)d_in[3];
    const float* W0    = (const float*)d_in[4];
    const float* b0    = (const float*)d_in[5];
    const float* convW = (const float*)d_in[6];
    const float* W1    = (const float*)d_in[7];
    const float* b1    = (const float*)d_in[8];
    float* out = (float*)d_out;

    float *pB, *pB2, *pB3, *pS, *pW0T, *ph, *ph0, *psup, *ptW;
    cudaGetSymbolAddress((void**)&pB,   g_Bmat);
    cudaGetSymbolAddress((void**)&pB2,  g_B2);
    cudaGetSymbolAddress((void**)&pB3,  g_B3);
    cudaGetSymbolAddress((void**)&pS,   g_S);
    cudaGetSymbolAddress((void**)&pW0T, g_W0T);
    cudaGetSymbolAddress((void**)&ph,   g_h);
    cudaGetSymbolAddress((void**)&ph0,  g_h0);
    cudaGetSymbolAddress((void**)&psup, g_sup);
    cudaGetSymbolAddress((void**)&ptW,  g_tW);

    // ---- orthogonalization of all 9 weight matrices (batched) ----
    k_center0<<<NH, 256>>>(W0);
    k_centerL<<<NLAY * NH, 256>>>(convW);
    k_cov<<<dim3(4, 4, NB), 256>>>();
    k_norm<<<NB, 256>>>();
    k_scaleinit<<<(NB * NH * NH) / 256, 256>>>();
    for (int it = 0; it < 5; it++) {
        k_ns<0><<<dim3(4, 4, NB), 256>>>(pB,  pB, pB2);   // B2 = B@B
        k_ns<0><<<dim3(4, 4, NB), 256>>>(pB2, pB, pB3);   // B3 = B2@B
        k_ns<1><<<dim3(4, 4, NB), 256>>>(pB3, pS, pB);    // B = 1.5B - 0.5*B3@S
    }
    k_wfinal<<<dim3(4, 8, NB), 256>>>();
    k_transpose<<<(NF * NH) / 256, 256>>>();

    // ---- input projection: h = relu(x @ W0o^T + b0), h0 = h ----
    const int MT = (NNODES + 127) / 128;
    k_gemm_big<<<dim3(MT, 2), 256>>>(x, pW0T, ph, ph0, b0, nullptr, NNODES, NF, 0.f, 0);

    // ---- CSR build (dst-sorted) ----
    k_zero<<<(NNODES + 255) / 256, 256>>>();
    k_hist<<<(NEDGES + 255) / 256, 256>>>(edst);
    const int NBLK = (NNODES + 1023) / 1024;
    k_scan1<<<NBLK, 1024>>>();
    k_scan2<<<1, 32>>>(NBLK);
    k_scan3<<<NBLK, 1024>>>();
    k_scatter<<<(NEDGES + 255) / 256, 256>>>(esrc, edst, ew);

    // ---- 8 GCNII layers ----
    for (int l = 1; l <= NLAY; l++) {
        float theta = logf(0.5f / (float)l + 1.f);
        k_spmm<<<NNODES / 4, 256>>>();
        k_gemm_big<<<dim3(MT, 2), 256>>>(psup, ptW + (size_t)(l - 1) * NH * NH,
                                         ph, nullptr, nullptr, psup, NNODES, NH, theta, 1);
    }

    // ---- classifier + log_softmax ----
    k_classifier<<<NNODES / 8, 320>>>(W1, b1, out);
}

// round 7
// speedup vs baseline: 1.0667x; 1.0667x over previous
#include <cuda_runtime.h>
#include <math.h>
#include <stdint.h>

#define NNODES 100000
#define NEDGES 3200000
#define NF 512
#define NH 256
#define NCLS 40
#define NLAY 8
#define NB 9            // ortho batches: W0 + 8 layer weights
#define EPSV 1e-5f
#define ALPHA 0.1f

// ---------------- device scratch (no runtime allocation allowed) ----------------
__device__ float g_h[(size_t)NNODES * NH];
__device__ float g_h0[(size_t)NNODES * NH];
__device__ float g_sup[(size_t)NNODES * NH];
__device__ float g_Zc0[NH * NF];
__device__ float g_ZcL[NLAY * NH * NH];
__device__ float g_S[NB * NH * NH];
__device__ float g_Bmat[NB * NH * NH];
__device__ float g_B2[NB * NH * NH];
__device__ float g_B3[NB * NH * NH];
__device__ float g_nrm[NB];
__device__ float g_W0o[NH * NF];
__device__ float g_W0T[NF * NH];
__device__ float g_tW[NLAY * NH * NH];
__device__ int   g_cnt[NNODES];
__device__ int   g_excl[NNODES];
__device__ int   g_bsum[128];
__device__ int   g_rowptr[NNODES + 1];
__device__ int   g_cursor[NNODES];
__device__ int   g_col[NEDGES];
__device__ float g_wt[NEDGES];

// ---------------- helpers ----------------
__device__ __forceinline__ float blk_reduce256(float v, float* red) {
    int t = threadIdx.x;
    red[t] = v; __syncthreads();
    for (int o = 128; o > 0; o >>= 1) {
        if (t < o) red[t] += red[t + o];
        __syncthreads();
    }
    return red[0];
}

// split x into (tf32_hi, tf32_lo) packed in float2
__device__ __forceinline__ float2 split2(float x) {
    uint32_t h; asm("cvt.rna.tf32.f32 %0, %1;" : "=r"(h) : "f"(x));
    float fh = __uint_as_float(h);
    float r = x - fh;
    uint32_t l; asm("cvt.rna.tf32.f32 %0, %1;" : "=r"(l) : "f"(r));
    return make_float2(fh, __uint_as_float(l));
}

__device__ __forceinline__ void mma_tf32(float c[4], const uint32_t a[4], const uint32_t b[2]) {
    asm volatile(
        "mma.sync.aligned.m16n8k8.row.col.f32.tf32.tf32.f32 "
        "{%0,%1,%2,%3},{%4,%5,%6,%7},{%8,%9},{%0,%1,%2,%3};\n"
        : "+f"(c[0]), "+f"(c[1]), "+f"(c[2]), "+f"(c[3])
        : "r"(a[0]), "r"(a[1]), "r"(a[2]), "r"(a[3]), "r"(b[0]), "r"(b[1]));
}

// ---------------- weight preprocessing ----------------
__global__ void k_center0(const float* __restrict__ W0) {
    __shared__ float red[256];
    int r = blockIdx.x;
    float s = 0.f;
    for (int c = threadIdx.x; c < NF; c += 256) s += W0[r * NF + c];
    float mean = blk_reduce256(s, red) / (float)NF;
    for (int c = threadIdx.x; c < NF; c += 256)
        g_Zc0[r * NF + c] = W0[r * NF + c] - mean;
}

__global__ void k_centerL(const float* __restrict__ convW) {
    __shared__ float red[256];
    int g = blockIdx.x;           // l*NH + r
    int l = g / NH, r = g % NH;
    int c = threadIdx.x;          // 256 threads == NH
    float v = 0.5f * convW[(size_t)l * NH * NH + r * NH + c] + (c == r ? 0.5f : 0.f);
    float mean = blk_reduce256(v, red) / (float)NH;
    g_ZcL[(size_t)l * NH * NH + r * NH + c] = v - mean;
}

// Batched covariance: S = Zc @ Zc^T + eps*I.
__global__ void __launch_bounds__(256) k_cov() {
    const int z = blockIdx.z;
    const int K = (z == 0) ? NF : NH;
    const float* A = (z == 0) ? g_Zc0 : (g_ZcL + (size_t)(z - 1) * NH * NH);
    float* C = g_S + (size_t)z * NH * NH;
    __shared__ float As[16][64];
    __shared__ float Bs[16][64];
    const int bi = blockIdx.x * 64, bj = blockIdx.y * 64;
    const int tid = threadIdx.x, tx = tid & 15, ty = tid >> 4;
    float acc[4][4] = {};
    for (int k0 = 0; k0 < K; k0 += 16) {
        int r = tid >> 2, kq = (tid & 3) << 2;
        float4 va = *(const float4*)(A + (size_t)(bi + r) * K + k0 + kq);
        As[kq][r] = va.x; As[kq + 1][r] = va.y; As[kq + 2][r] = va.z; As[kq + 3][r] = va.w;
        float4 vb = *(const float4*)(A + (size_t)(bj + r) * K + k0 + kq);
        Bs[kq][r] = vb.x; Bs[kq + 1][r] = vb.y; Bs[kq + 2][r] = vb.z; Bs[kq + 3][r] = vb.w;
        __syncthreads();
#pragma unroll
        for (int k = 0; k < 16; k++) {
            float a[4], b[4];
#pragma unroll
            for (int i = 0; i < 4; i++) a[i] = As[k][ty * 4 + i];
#pragma unroll
            for (int j = 0; j < 4; j++) b[j] = Bs[k][tx * 4 + j];
#pragma unroll
            for (int i = 0; i < 4; i++)
#pragma unroll
                for (int j = 0; j < 4; j++) acc[i][j] = fmaf(a[i], b[j], acc[i][j]);
        }
        __syncthreads();
    }
#pragma unroll
    for (int i = 0; i < 4; i++)
#pragma unroll
        for (int j = 0; j < 4; j++) {
            int gi = bi + ty * 4 + i, gj = bj + tx * 4 + j;
            float v = acc[i][j];
            if (gi == gj) v += EPSV;
            C[(size_t)gi * NH + gj] = v;
        }
}

__global__ void k_norm() {
    __shared__ float red[256];
    const int z = blockIdx.x;
    const float* S = g_S + (size_t)z * NH * NH;
    float s = 0.f;
    for (int i = threadIdx.x; i < NH * NH; i += 256) { float v = S[i]; s += v * v; }
    float tot = blk_reduce256(s, red);
    if (threadIdx.x == 0) g_nrm[z] = sqrtf(tot);
}

__global__ void k_scaleinit() {
    int idx = blockIdx.x * 256 + threadIdx.x;
    int z = idx >> 16;
    int i = (idx >> 8) & 255, j = idx & 255;
    float inv = 1.f / g_nrm[z];
    g_S[idx] *= inv;
    g_Bmat[idx] = (i == j) ? 1.f : 0.f;
}

// Batched 256x256x256 NN GEMM.  MODE 0: C = A@B ;  MODE 1: C = 1.5*C - 0.5*(A@B)
template <int MODE>
__global__ void __launch_bounds__(256) k_ns(const float* __restrict__ Ab,
                                            const float* __restrict__ Bb,
                                            float* __restrict__ Cb) {
    const int z = blockIdx.z;
    const float* A = Ab + (size_t)z * NH * NH;
    const float* B = Bb + (size_t)z * NH * NH;
    float* C = Cb + (size_t)z * NH * NH;
    __shared__ float As[16][64];
    __shared__ float Bs[16][64];
    const int bi = blockIdx.x * 64, bj = blockIdx.y * 64;
    const int tid = threadIdx.x, tx = tid & 15, ty = tid >> 4;
    float acc[4][4] = {};
    for (int k0 = 0; k0 < NH; k0 += 16) {
        { int r = tid >> 2, kq = (tid & 3) << 2;
          float4 v = *(const float4*)(A + (size_t)(bi + r) * NH + k0 + kq);
          As[kq][r] = v.x; As[kq + 1][r] = v.y; As[kq + 2][r] = v.z; As[kq + 3][r] = v.w; }
        { int kr = tid >> 4, nc = (tid & 15) << 2;
          *(float4*)&Bs[kr][nc] = *(const float4*)(B + (size_t)(k0 + kr) * NH + bj + nc); }
        __syncthreads();
#pragma unroll
        for (int k = 0; k < 16; k++) {
            float a[4], b[4];
#pragma unroll
            for (int i = 0; i < 4; i++) a[i] = As[k][ty * 4 + i];
#pragma unroll
            for (int j = 0; j < 4; j++) b[j] = Bs[k][tx * 4 + j];
#pragma unroll
            for (int i = 0; i < 4; i++)
#pragma unroll
                for (int j = 0; j < 4; j++) acc[i][j] = fmaf(a[i], b[j], acc[i][j]);
        }
        __syncthreads();
    }
#pragma unroll
    for (int i = 0; i < 4; i++)
#pragma unroll
        for (int j = 0; j < 4; j++) {
            int gi = bi + ty * 4 + i, gj = bj + tx * 4 + j;
            size_t off = (size_t)gi * NH + gj;
            if (MODE == 0) C[off] = acc[i][j];
            else           C[off] = 1.5f * C[off] - 0.5f * acc[i][j];
        }
}

// W_out = (B_t @ Zc) * rsqrt(norm).
__global__ void __launch_bounds__(256) k_wfinal() {
    const int z = blockIdx.z;
    const int Nz = (z == 0) ? NF : NH;
    if (blockIdx.y * 64 >= Nz) return;
    const float* A = g_Bmat + (size_t)z * NH * NH;
    const float* B = (z == 0) ? g_Zc0 : (g_ZcL + (size_t)(z - 1) * NH * NH);
    float* C = (z == 0) ? g_W0o : (g_tW + (size_t)(z - 1) * NH * NH);
    __shared__ float As[16][64];
    __shared__ float Bs[16][64];
    const int bi = blockIdx.x * 64, bj = blockIdx.y * 64;
    const int tid = threadIdx.x, tx = tid & 15, ty = tid >> 4;
    float acc[4][4] = {};
    for (int k0 = 0; k0 < NH; k0 += 16) {
        { int r = tid >> 2, kq = (tid & 3) << 2;
          float4 v = *(const float4*)(A + (size_t)(bi + r) * NH + k0 + kq);
          As[kq][r] = v.x; As[kq + 1][r] = v.y; As[kq + 2][r] = v.z; As[kq + 3][r] = v.w; }
        { int kr = tid >> 4, nc = (tid & 15) << 2;
          *(float4*)&Bs[kr][nc] = *(const float4*)(B + (size_t)(k0 + kr) * Nz + bj + nc); }
        __syncthreads();
#pragma unroll
        for (int k = 0; k < 16; k++) {
            float a[4], b[4];
#pragma unroll
            for (int i = 0; i < 4; i++) a[i] = As[k][ty * 4 + i];
#pragma unroll
            for (int j = 0; j < 4; j++) b[j] = Bs[k][tx * 4 + j];
#pragma unroll
            for (int i = 0; i < 4; i++)
#pragma unroll
                for (int j = 0; j < 4; j++) acc[i][j] = fmaf(a[i], b[j], acc[i][j]);
        }
        __syncthreads();
    }
    float sc = rsqrtf(g_nrm[z]);
#pragma unroll
    for (int i = 0; i < 4; i++)
#pragma unroll
        for (int j = 0; j < 4; j++) {
            int gi = bi + ty * 4 + i, gj = bj + tx * 4 + j;
            C[(size_t)gi * Nz + gj] = acc[i][j] * sc;
        }
}

__global__ void k_transpose() {
    int idx = blockIdx.x * 256 + threadIdx.x;   // < NF*NH
    int k = idx >> 8, n = idx & 255;
    g_W0T[idx] = g_W0o[(size_t)n * NF + k];
}

// ---------------- big fused GEMM on tensor cores (3xTF32), N = 256 fixed ----------------
// mode 0: C = relu(A@B + bias), C2 = C
// mode 1: C = relu(theta*(A@B) + (1-theta)*R)
// Block tile 128x128x32, 8 warps (2x4), warp tile 64x32, double-buffered smem.
#define TSTR 133              // float2 row stride (<=2-way bank conflicts)
#define SAS (32 * TSTR)       // one buffer (A or B): 32 k-rows

__global__ void __launch_bounds__(256) k_gemm_tc(
    const float* __restrict__ A, const float* __restrict__ B,
    float* __restrict__ C, float* __restrict__ C2,
    const float* __restrict__ bias, const float* __restrict__ R,
    int M, int K, float theta, int mode) {
    extern __shared__ float2 smem[];
    float2* As = smem;              // [2][32][TSTR]  (k-major, m contiguous)
    float2* Bs = smem + 2 * SAS;    // [2][32][TSTR]  (k-major, n contiguous)

    const int tid = threadIdx.x;
    const int lane = tid & 31, warp = tid >> 5;
    const int wm = warp >> 2, wn = warp & 3;     // 2 x 4 warp grid
    const int bm = blockIdx.x * 128, bn = blockIdx.y * 128;
    const int lr = tid >> 3;      // 0..31
    const int lq = tid & 7;       // 0..7
    const int g = lane >> 2, lc = lane & 3;

    float c[4][4][4];
#pragma unroll
    for (int i = 0; i < 4; i++)
#pragma unroll
        for (int j = 0; j < 4; j++)
#pragma unroll
            for (int e = 0; e < 4; e++) c[i][j][e] = 0.f;

    float4 pa[4], pb[4];
    const int nit = K / 32;

    // ---- prefetch iter 0 ----
#pragma unroll
    for (int i = 0; i < 4; i++) {
        int gm = bm + lr + i * 32;
        pa[i] = (gm < M) ? *(const float4*)(A + (size_t)gm * K + lq * 4)
                         : make_float4(0.f, 0.f, 0.f, 0.f);
        pb[i] = *(const float4*)(B + (size_t)lr * NH + bn + (lq + i * 8) * 4);
    }
    // ---- store iter 0 ----
    {
        float2* dA = As; float2* dB = Bs;
#pragma unroll
        for (int i = 0; i < 4; i++) {
            int row = lr + i * 32;
            float va[4] = {pa[i].x, pa[i].y, pa[i].z, pa[i].w};
            float vb[4] = {pb[i].x, pb[i].y, pb[i].z, pb[i].w};
#pragma unroll
            for (int e = 0; e < 4; e++) {
                dA[(lq * 4 + e) * TSTR + row] = split2(va[e]);
                dB[lr * TSTR + (lq + i * 8) * 4 + e] = split2(vb[e]);
            }
        }
    }
    __syncthreads();

    for (int it = 0; it < nit; it++) {
        const int buf = it & 1;
        // prefetch next tile (global -> regs)
        if (it + 1 < nit) {
            const int k0 = (it + 1) * 32;
#pragma unroll
            for (int i = 0; i < 4; i++) {
                int gm = bm + lr + i * 32;
                pa[i] = (gm < M) ? *(const float4*)(A + (size_t)gm * K + k0 + lq * 4)
                                 : make_float4(0.f, 0.f, 0.f, 0.f);
                pb[i] = *(const float4*)(B + (size_t)(k0 + lr) * NH + bn + (lq + i * 8) * 4);
            }
        }
        // compute on current buffer
        {
            const float2* Ab = As + buf * SAS;
            const float2* Bb = Bs + buf * SAS;
#pragma unroll
            for (int ks = 0; ks < 4; ks++) {
                const int kb = ks * 8;
                uint32_t ah[4][4], al[4][4], bh[4][2], bl[4][2];
#pragma unroll
                for (int mt = 0; mt < 4; mt++) {
                    int m0 = wm * 64 + mt * 16 + g;
                    float2 v00 = Ab[(kb + lc) * TSTR + m0];
                    float2 v10 = Ab[(kb + lc) * TSTR + m0 + 8];
                    float2 v01 = Ab[(kb + lc + 4) * TSTR + m0];
                    float2 v11 = Ab[(kb + lc + 4) * TSTR + m0 + 8];
                    ah[mt][0] = __float_as_uint(v00.x); al[mt][0] = __float_as_uint(v00.y);
                    ah[mt][1] = __float_as_uint(v10.x); al[mt][1] = __float_as_uint(v10.y);
                    ah[mt][2] = __float_as_uint(v01.x); al[mt][2] = __float_as_uint(v01.y);
                    ah[mt][3] = __float_as_uint(v11.x); al[mt][3] = __float_as_uint(v11.y);
                }
#pragma unroll
                for (int nt = 0; nt < 4; nt++) {
                    int n0 = wn * 32 + nt * 8 + g;
                    float2 b0 = Bb[(kb + lc) * TSTR + n0];
                    float2 b1 = Bb[(kb + lc + 4) * TSTR + n0];
                    bh[nt][0] = __float_as_uint(b0.x); bl[nt][0] = __float_as_uint(b0.y);
                    bh[nt][1] = __float_as_uint(b1.x); bl[nt][1] = __float_as_uint(b1.y);
                }
#pragma unroll
                for (int mt = 0; mt < 4; mt++)
#pragma unroll
                    for (int nt = 0; nt < 4; nt++) {
                        mma_tf32(c[mt][nt], ah[mt], bh[nt]);
                        mma_tf32(c[mt][nt], ah[mt], bl[nt]);
                        mma_tf32(c[mt][nt], al[mt], bh[nt]);
                    }
            }
        }
        // store next tile into other buffer
        if (it + 1 < nit) {
            float2* dA = As + (buf ^ 1) * SAS;
            float2* dB = Bs + (buf ^ 1) * SAS;
#pragma unroll
            for (int i = 0; i < 4; i++) {
                int row = lr + i * 32;
                float va[4] = {pa[i].x, pa[i].y, pa[i].z, pa[i].w};
                float vb[4] = {pb[i].x, pb[i].y, pb[i].z, pb[i].w};
#pragma unroll
                for (int e = 0; e < 4; e++) {
                    dA[(lq * 4 + e) * TSTR + row] = split2(va[e]);
                    dB[lr * TSTR + (lq + i * 8) * 4 + e] = split2(vb[e]);
                }
            }
            __syncthreads();
        }
    }

    // ---- epilogue ----
    const float om_theta = 1.f - theta;
#pragma unroll
    for (int mt = 0; mt < 4; mt++) {
#pragma unroll
        for (int half = 0; half < 2; half++) {
            int row = bm + wm * 64 + mt * 16 + g + half * 8;
            if (row >= M) continue;
#pragma unroll
            for (int nt = 0; nt < 4; nt++) {
                int col = bn + wn * 32 + nt * 8 + 2 * lc;
                size_t off = (size_t)row * NH + col;
                float vx = c[mt][nt][2 * half];
                float vy = c[mt][nt][2 * half + 1];
                if (mode == 0) {
                    vx += bias[col];     vy += bias[col + 1];
                    vx = vx > 0.f ? vx : 0.f;
                    vy = vy > 0.f ? vy : 0.f;
                    *(float2*)(C + off)  = make_float2(vx, vy);
                    *(float2*)(C2 + off) = make_float2(vx, vy);
                } else {
                    float2 r = *(const float2*)(R + off);
                    vx = theta * vx + om_theta * r.x;
                    vy = theta * vy + om_theta * r.y;
                    vx = vx > 0.f ? vx : 0.f;
                    vy = vy > 0.f ? vy : 0.f;
                    *(float2*)(C + off) = make_float2(vx, vy);
                }
            }
        }
    }
}

// ---------------- CSR build ----------------
__global__ void k_zero() {
    int i = blockIdx.x * 256 + threadIdx.x;
    if (i < NNODES) g_cnt[i] = 0;
}
__global__ void k_hist(const int* __restrict__ edst) {
    int i = blockIdx.x * 256 + threadIdx.x;
    if (i < NEDGES) atomicAdd(&g_cnt[edst[i]], 1);
}
__global__ void k_scan1() {
    __shared__ int s[1024];
    int i = blockIdx.x * 1024 + threadIdx.x;
    int v = (i < NNODES) ? g_cnt[i] : 0;
    s[threadIdx.x] = v;
    __syncthreads();
    for (int off = 1; off < 1024; off <<= 1) {
        int t = 0;
        if (threadIdx.x >= off) t = s[threadIdx.x - off];
        __syncthreads();
        if (threadIdx.x >= off) s[threadIdx.x] += t;
        __syncthreads();
    }
    if (i < NNODES) g_excl[i] = s[threadIdx.x] - v;
    if (threadIdx.x == 1023) g_bsum[blockIdx.x] = s[1023];
}
__global__ void k_scan2(int nb) {
    if (threadIdx.x == 0) {
        int run = 0;
        for (int i = 0; i < nb; i++) { int t = g_bsum[i]; g_bsum[i] = run; run += t; }
    }
}
__global__ void k_scan3() {
    int i = blockIdx.x * 1024 + threadIdx.x;
    if (i < NNODES) {
        int v = g_excl[i] + g_bsum[i >> 10];
        g_rowptr[i] = v;
        g_cursor[i] = v;
    }
    if (i == 0) g_rowptr[NNODES] = NEDGES;
}
__global__ void k_scatter(const int* __restrict__ esrc, const int* __restrict__ edst,
                          const float* __restrict__ ew) {
    int i = blockIdx.x * 256 + threadIdx.x;
    if (i < NEDGES) {
        int d = edst[i];
        int pos = atomicAdd(&g_cursor[d], 1);
        g_col[pos] = esrc[i];
        g_wt[pos]  = ew[i];
    }
}

// ---------------- SpMM + support fusion ----------------
__global__ void __launch_bounds__(256) k_spmm() {
    const int node = blockIdx.x * 4 + (threadIdx.x >> 6);
    const int lane = threadIdx.x & 63;
    const int rs = g_rowptr[node];
    const int re = g_rowptr[node + 1];
    float ax = 0.f, ay = 0.f, az = 0.f, aw = 0.f;
    int p = rs;
    for (; p + 2 <= re; p += 2) {
        int s0 = __ldg(&g_col[p]);
        int s1 = __ldg(&g_col[p + 1]);
        float w0 = __ldg(&g_wt[p]);
        float w1 = __ldg(&g_wt[p + 1]);
        float4 v0 = __ldg((const float4*)(g_h + (size_t)s0 * NH) + lane);
        float4 v1 = __ldg((const float4*)(g_h + (size_t)s1 * NH) + lane);
        ax = fmaf(w0, v0.x, ax); ay = fmaf(w0, v0.y, ay);
        az = fmaf(w0, v0.z, az); aw = fmaf(w0, v0.w, aw);
        ax = fmaf(w1, v1.x, ax); ay = fmaf(w1, v1.y, ay);
        az = fmaf(w1, v1.z, az); aw = fmaf(w1, v1.w, aw);
    }
    if (p < re) {
        int s0 = __ldg(&g_col[p]);
        float w0 = __ldg(&g_wt[p]);
        float4 v0 = __ldg((const float4*)(g_h + (size_t)s0 * NH) + lane);
        ax = fmaf(w0, v0.x, ax); ay = fmaf(w0, v0.y, ay);
        az = fmaf(w0, v0.z, az); aw = fmaf(w0, v0.w, aw);
    }
    float4 r = __ldg((const float4*)(g_h0 + (size_t)node * NH) + lane);
    float4 o;
    o.x = 0.9f * ax + ALPHA * r.x;
    o.y = 0.9f * ay + ALPHA * r.y;
    o.z = 0.9f * az + ALPHA * r.z;
    o.w = 0.9f * aw + ALPHA * r.w;
    *((float4*)(g_sup + (size_t)node * NH) + lane) = o;
}

// ---------------- classifier + log_softmax ----------------
__global__ void __launch_bounds__(320) k_classifier(const float* __restrict__ W1,
                                                    const float* __restrict__ b1,
                                                    float* __restrict__ out) {
    __shared__ float W1s[NCLS * 257];
    __shared__ float logits[8][41];
    __shared__ float mx[8], lse[8];
    const int tid = threadIdx.x;
    for (int idx = tid; idx < NCLS * NH; idx += 320) {
        int c = idx >> 8, k = idx & 255;
        W1s[c * 257 + k] = W1[idx];
    }
    __syncthreads();
    const int ln = tid / NCLS;
    const int c  = tid % NCLS;
    const int node = blockIdx.x * 8 + ln;
    const float* hrow = g_h + (size_t)node * NH;
    float acc = __ldg(&b1[c]);
#pragma unroll 4
    for (int k = 0; k < NH; k++)
        acc = fmaf(__ldg(hrow + k), W1s[c * 257 + k], acc);
    logits[ln][c] = acc;
    __syncthreads();
    if (tid < 8) {
        float m = -1e30f;
        for (int j = 0; j < NCLS; j++) m = fmaxf(m, logits[tid][j]);
        float s = 0.f;
        for (int j = 0; j < NCLS; j++) s += expf(logits[tid][j] - m);
        mx[tid] = m;
        lse[tid] = logf(s);
    }
    __syncthreads();
    out[(size_t)node * NCLS + c] = logits[ln][c] - mx[ln] - lse[ln];
}

// ---------------- launch ----------------
extern "C" void kernel_launch(void* const* d_in, const int* in_sizes, int n_in,
                              void* d_out, int out_size) {
    const float* x     = (const float*)d_in[0];
    const int*   esrc  = (const int*)d_in[1];
    const int*   edst  = (const int*)d_in[2];
    const float* ew    = (const float*)d_in[3];
    const float* W0    = (const float*)d_in[4];
    const float* b0    = (const float*)d_in[5];
    const float* convW = (const float*)d_in[6];
    const float* W1    = (const float*)d_in[7];
    const float* b1    = (const float*)d_in[8];
    float* out = (float*)d_out;

    float *pB, *pB2, *pB3, *pS, *pW0T, *ph, *ph0, *psup, *ptW;
    cudaGetSymbolAddress((void**)&pB,   g_Bmat);
    cudaGetSymbolAddress((void**)&pB2,  g_B2);
    cudaGetSymbolAddress((void**)&pB3,  g_B3);
    cudaGetSymbolAddress((void**)&pS,   g_S);
    cudaGetSymbolAddress((void**)&pW0T, g_W0T);
    cudaGetSymbolAddress((void**)&ph,   g_h);
    cudaGetSymbolAddress((void**)&ph0,  g_h0);
    cudaGetSymbolAddress((void**)&psup, g_sup);
    cudaGetSymbolAddress((void**)&ptW,  g_tW);

    const int SMEM_TC = 4 * SAS * (int)sizeof(float2);   // 136,192 B
    cudaFuncSetAttribute(k_gemm_tc, cudaFuncAttributeMaxDynamicSharedMemorySize, SMEM_TC);

    // ---- orthogonalization of all 9 weight matrices (batched) ----
    k_center0<<<NH, 256>>>(W0);
    k_centerL<<<NLAY * NH, 256>>>(convW);
    k_cov<<<dim3(4, 4, NB), 256>>>();
    k_norm<<<NB, 256>>>();
    k_scaleinit<<<(NB * NH * NH) / 256, 256>>>();
    for (int it = 0; it < 5; it++) {
        k_ns<0><<<dim3(4, 4, NB), 256>>>(pB,  pB, pB2);   // B2 = B@B
        k_ns<0><<<dim3(4, 4, NB), 256>>>(pB2, pB, pB3);   // B3 = B2@B
        k_ns<1><<<dim3(4, 4, NB), 256>>>(pB3, pS, pB);    // B = 1.5B - 0.5*B3@S
    }
    k_wfinal<<<dim3(4, 8, NB), 256>>>();
    k_transpose<<<(NF * NH) / 256, 256>>>();

    // ---- input projection: h = relu(x @ W0o^T + b0), h0 = h ----
    const int MT = (NNODES + 127) / 128;
    k_gemm_tc<<<dim3(MT, 2), 256, SMEM_TC>>>(x, pW0T, ph, ph0, b0, nullptr,
                                             NNODES, NF, 0.f, 0);

    // ---- CSR build (dst-sorted) ----
    k_zero<<<(NNODES + 255) / 256, 256>>>();
    k_hist<<<(NEDGES + 255) / 256, 256>>>(edst);
    const int NBLK = (NNODES + 1023) / 1024;
    k_scan1<<<NBLK, 1024>>>();
    k_scan2<<<1, 32>>>(NBLK);
    k_scan3<<<NBLK, 1024>>>();
    k_scatter<<<(NEDGES + 255) / 256, 256>>>(esrc, edst, ew);

    // ---- 8 GCNII layers ----
    for (int l = 1; l <= NLAY; l++) {
        float theta = logf(0.5f / (float)l + 1.f);
        k_spmm<<<NNODES / 4, 256>>>();
        k_gemm_tc<<<dim3(MT, 2), 256, SMEM_TC>>>(psup, ptW + (size_t)(l - 1) * NH * NH,
                                                 ph, nullptr, nullptr, psup,
                                                 NNODES, NH, theta, 1);
    }

    // ---- classifier + log_softmax ----
    k_classifier<<<NNODES / 8, 320>>>(W1, b1, out);
}

// round 9
// speedup vs baseline: 1.1201x; 1.0501x over previous
#include <cuda_runtime.h>
#include <math.h>
#include <stdint.h>

#define NNODES 100000
#define NEDGES 3200000
#define NF 512
#define NH 256
#define NCLS 40
#define NLAY 8
#define NB 9            // ortho batches: W0 + 8 layer weights
#define EPSV 1e-5f
#define ALPHA 0.1f

// ---------------- device scratch (no runtime allocation allowed) ----------------
__device__ float g_h[(size_t)NNODES * NH];
__device__ float g_h0[(size_t)NNODES * NH];
__device__ float g_sup[(size_t)NNODES * NH];
__device__ float g_Zc0[NH * NF];
__device__ float g_ZcL[NLAY * NH * NH];
__device__ float g_S[NB * NH * NH];
__device__ float g_Bmat[NB * NH * NH];
__device__ float g_B2[NB * NH * NH];
__device__ float g_B3[NB * NH * NH];
__device__ float g_nrm[NB];
__device__ float g_W0o[NH * NF];
__device__ float g_W0T[NF * NH];
__device__ float g_tW[NLAY * NH * NH];
__device__ int   g_cnt[NNODES];
__device__ int   g_excl[NNODES];
__device__ int   g_bsum[128];
__device__ int   g_rowptr[NNODES + 1];
__device__ int   g_cursor[NNODES];
__device__ int   g_col[NEDGES];
__device__ float g_wt[NEDGES];

// ---------------- helpers ----------------
__device__ __forceinline__ float blk_reduce256(float v, float* red) {
    int t = threadIdx.x;
    red[t] = v; __syncthreads();
    for (int o = 128; o > 0; o >>= 1) {
        if (t < o) red[t] += red[t + o];
        __syncthreads();
    }
    return red[0];
}

// split x into (tf32_hi, tf32_lo) packed in float2
__device__ __forceinline__ float2 split2(float x) {
    uint32_t h; asm("cvt.rna.tf32.f32 %0, %1;" : "=r"(h) : "f"(x));
    float fh = __uint_as_float(h);
    float r = x - fh;
    uint32_t l; asm("cvt.rna.tf32.f32 %0, %1;" : "=r"(l) : "f"(r));
    return make_float2(fh, __uint_as_float(l));
}

__device__ __forceinline__ void mma_tf32(float c[4], const uint32_t a[4], const uint32_t b[2]) {
    asm volatile(
        "mma.sync.aligned.m16n8k8.row.col.f32.tf32.tf32.f32 "
        "{%0,%1,%2,%3},{%4,%5,%6,%7},{%8,%9},{%0,%1,%2,%3};\n"
        : "+f"(c[0]), "+f"(c[1]), "+f"(c[2]), "+f"(c[3])
        : "r"(a[0]), "r"(a[1]), "r"(a[2]), "r"(a[3]), "r"(b[0]), "r"(b[1]));
}

// ---------------- weight preprocessing ----------------
__global__ void k_center0(const float* __restrict__ W0) {
    __shared__ float red[256];
    int r = blockIdx.x;
    float s = 0.f;
    for (int c = threadIdx.x; c < NF; c += 256) s += W0[r * NF + c];
    float mean = blk_reduce256(s, red) / (float)NF;
    for (int c = threadIdx.x; c < NF; c += 256)
        g_Zc0[r * NF + c] = W0[r * NF + c] - mean;
}

__global__ void k_centerL(const float* __restrict__ convW) {
    __shared__ float red[256];
    int g = blockIdx.x;           // l*NH + r
    int l = g / NH, r = g % NH;
    int c = threadIdx.x;          // 256 threads == NH
    float v = 0.5f * convW[(size_t)l * NH * NH + r * NH + c] + (c == r ? 0.5f : 0.f);
    float mean = blk_reduce256(v, red) / (float)NH;
    g_ZcL[(size_t)l * NH * NH + r * NH + c] = v - mean;
}

// Batched covariance: S = Zc @ Zc^T + eps*I.
__global__ void __launch_bounds__(256) k_cov() {
    const int z = blockIdx.z;
    const int K = (z == 0) ? NF : NH;
    const float* A = (z == 0) ? g_Zc0 : (g_ZcL + (size_t)(z - 1) * NH * NH);
    float* C = g_S + (size_t)z * NH * NH;
    __shared__ float As[16][64];
    __shared__ float Bs[16][64];
    const int bi = blockIdx.x * 64, bj = blockIdx.y * 64;
    const int tid = threadIdx.x, tx = tid & 15, ty = tid >> 4;
    float acc[4][4] = {};
    for (int k0 = 0; k0 < K; k0 += 16) {
        int r = tid >> 2, kq = (tid & 3) << 2;
        float4 va = *(const float4*)(A + (size_t)(bi + r) * K + k0 + kq);
        As[kq][r] = va.x; As[kq + 1][r] = va.y; As[kq + 2][r] = va.z; As[kq + 3][r] = va.w;
        float4 vb = *(const float4*)(A + (size_t)(bj + r) * K + k0 + kq);
        Bs[kq][r] = vb.x; Bs[kq + 1][r] = vb.y; Bs[kq + 2][r] = vb.z; Bs[kq + 3][r] = vb.w;
        __syncthreads();
#pragma unroll
        for (int k = 0; k < 16; k++) {
            float a[4], b[4];
#pragma unroll
            for (int i = 0; i < 4; i++) a[i] = As[k][ty * 4 + i];
#pragma unroll
            for (int j = 0; j < 4; j++) b[j] = Bs[k][tx * 4 + j];
#pragma unroll
            for (int i = 0; i < 4; i++)
#pragma unroll
                for (int j = 0; j < 4; j++) acc[i][j] = fmaf(a[i], b[j], acc[i][j]);
        }
        __syncthreads();
    }
#pragma unroll
    for (int i = 0; i < 4; i++)
#pragma unroll
        for (int j = 0; j < 4; j++) {
            int gi = bi + ty * 4 + i, gj = bj + tx * 4 + j;
            float v = acc[i][j];
            if (gi == gj) v += EPSV;
            C[(size_t)gi * NH + gj] = v;
        }
}

__global__ void k_norm() {
    __shared__ float red[256];
    const int z = blockIdx.x;
    const float* S = g_S + (size_t)z * NH * NH;
    float s = 0.f;
    for (int i = threadIdx.x; i < NH * NH; i += 256) { float v = S[i]; s += v * v; }
    float tot = blk_reduce256(s, red);
    if (threadIdx.x == 0) g_nrm[z] = sqrtf(tot);
}

__global__ void k_scaleinit() {
    int idx = blockIdx.x * 256 + threadIdx.x;
    int z = idx >> 16;
    int i = (idx >> 8) & 255, j = idx & 255;
    float inv = 1.f / g_nrm[z];
    g_S[idx] *= inv;
    g_Bmat[idx] = (i == j) ? 1.f : 0.f;
}

// Batched 256x256x256 NN GEMM.  MODE 0: C = A@B ;  MODE 1: C = 1.5*C - 0.5*(A@B)
template <int MODE>
__global__ void __launch_bounds__(256) k_ns(const float* __restrict__ Ab,
                                            const float* __restrict__ Bb,
                                            float* __restrict__ Cb) {
    const int z = blockIdx.z;
    const float* A = Ab + (size_t)z * NH * NH;
    const float* B = Bb + (size_t)z * NH * NH;
    float* C = Cb + (size_t)z * NH * NH;
    __shared__ float As[16][64];
    __shared__ float Bs[16][64];
    const int bi = blockIdx.x * 64, bj = blockIdx.y * 64;
    const int tid = threadIdx.x, tx = tid & 15, ty = tid >> 4;
    float acc[4][4] = {};
    for (int k0 = 0; k0 < NH; k0 += 16) {
        { int r = tid >> 2, kq = (tid & 3) << 2;
          float4 v = *(const float4*)(A + (size_t)(bi + r) * NH + k0 + kq);
          As[kq][r] = v.x; As[kq + 1][r] = v.y; As[kq + 2][r] = v.z; As[kq + 3][r] = v.w; }
        { int kr = tid >> 4, nc = (tid & 15) << 2;
          *(float4*)&Bs[kr][nc] = *(const float4*)(B + (size_t)(k0 + kr) * NH + bj + nc); }
        __syncthreads();
#pragma unroll
        for (int k = 0; k < 16; k++) {
            float a[4], b[4];
#pragma unroll
            for (int i = 0; i < 4; i++) a[i] = As[k][ty * 4 + i];
#pragma unroll
            for (int j = 0; j < 4; j++) b[j] = Bs[k][tx * 4 + j];
#pragma unroll
            for (int i = 0; i < 4; i++)
#pragma unroll
                for (int j = 0; j < 4; j++) acc[i][j] = fmaf(a[i], b[j], acc[i][j]);
        }
        __syncthreads();
    }
#pragma unroll
    for (int i = 0; i < 4; i++)
#pragma unroll
        for (int j = 0; j < 4; j++) {
            int gi = bi + ty * 4 + i, gj = bj + tx * 4 + j;
            size_t off = (size_t)gi * NH + gj;
            if (MODE == 0) C[off] = acc[i][j];
            else           C[off] = 1.5f * C[off] - 0.5f * acc[i][j];
        }
}

// W_out = (B_t @ Zc) * rsqrt(norm).
__global__ void __launch_bounds__(256) k_wfinal() {
    const int z = blockIdx.z;
    const int Nz = (z == 0) ? NF : NH;
    if (blockIdx.y * 64 >= Nz) return;
    const float* A = g_Bmat + (size_t)z * NH * NH;
    const float* B = (z == 0) ? g_Zc0 : (g_ZcL + (size_t)(z - 1) * NH * NH);
    float* C = (z == 0) ? g_W0o : (g_tW + (size_t)(z - 1) * NH * NH);
    __shared__ float As[16][64];
    __shared__ float Bs[16][64];
    const int bi = blockIdx.x * 64, bj = blockIdx.y * 64;
    const int tid = threadIdx.x, tx = tid & 15, ty = tid >> 4;
    float acc[4][4] = {};
    for (int k0 = 0; k0 < NH; k0 += 16) {
        { int r = tid >> 2, kq = (tid & 3) << 2;
          float4 v = *(const float4*)(A + (size_t)(bi + r) * NH + k0 + kq);
          As[kq][r] = v.x; As[kq + 1][r] = v.y; As[kq + 2][r] = v.z; As[kq + 3][r] = v.w; }
        { int kr = tid >> 4, nc = (tid & 15) << 2;
          *(float4*)&Bs[kr][nc] = *(const float4*)(B + (size_t)(k0 + kr) * Nz + bj + nc); }
        __syncthreads();
#pragma unroll
        for (int k = 0; k < 16; k++) {
            float a[4], b[4];
#pragma unroll
            for (int i = 0; i < 4; i++) a[i] = As[k][ty * 4 + i];
#pragma unroll
            for (int j = 0; j < 4; j++) b[j] = Bs[k][tx * 4 + j];
#pragma unroll
            for (int i = 0; i < 4; i++)
#pragma unroll
                for (int j = 0; j < 4; j++) acc[i][j] = fmaf(a[i], b[j], acc[i][j]);
        }
        __syncthreads();
    }
    float sc = rsqrtf(g_nrm[z]);
#pragma unroll
    for (int i = 0; i < 4; i++)
#pragma unroll
        for (int j = 0; j < 4; j++) {
            int gi = bi + ty * 4 + i, gj = bj + tx * 4 + j;
            C[(size_t)gi * Nz + gj] = acc[i][j] * sc;
        }
}

__global__ void k_transpose() {
    int idx = blockIdx.x * 256 + threadIdx.x;   // < NF*NH
    int k = idx >> 8, n = idx & 255;
    g_W0T[idx] = g_W0o[(size_t)n * NF + k];
}

// ---------------- big fused GEMM on tensor cores (3xTF32), N = 256 fixed ----------------
// mode 0: C = relu(A@B + bias), C2 = C
// mode 1: C = relu(theta*(A@B) + (1-theta)*R)
// Block tile 128x128x32, 8 warps (2x4), warp tile 64x32, double-buffered smem.
#define TSTR 133              // float2 row stride (<=2-way bank conflicts)
#define SAS (32 * TSTR)       // one buffer (A or B): 32 k-rows

__global__ void __launch_bounds__(256) k_gemm_tc(
    const float* __restrict__ A, const float* __restrict__ B,
    float* __restrict__ C, float* __restrict__ C2,
    const float* __restrict__ bias, const float* __restrict__ R,
    int M, int K, float theta, int mode) {
    extern __shared__ float2 smem[];
    float2* As = smem;              // [2][32][TSTR]  (k-major, m contiguous)
    float2* Bs = smem + 2 * SAS;    // [2][32][TSTR]  (k-major, n contiguous)

    const int tid = threadIdx.x;
    const int lane = tid & 31, warp = tid >> 5;
    const int wm = warp >> 2, wn = warp & 3;     // 2 x 4 warp grid
    const int bm = blockIdx.x * 128, bn = blockIdx.y * 128;
    const int lr = tid >> 3;      // 0..31
    const int lq = tid & 7;       // 0..7
    const int g = lane >> 2, lc = lane & 3;

    float c[4][4][4];
#pragma unroll
    for (int i = 0; i < 4; i++)
#pragma unroll
        for (int j = 0; j < 4; j++)
#pragma unroll
            for (int e = 0; e < 4; e++) c[i][j][e] = 0.f;

    float4 pa[4], pb[4];
    const int nit = K / 32;

    // ---- prefetch iter 0 ----
#pragma unroll
    for (int i = 0; i < 4; i++) {
        int gm = bm + lr + i * 32;
        pa[i] = (gm < M) ? *(const float4*)(A + (size_t)gm * K + lq * 4)
                         : make_float4(0.f, 0.f, 0.f, 0.f);
        pb[i] = *(const float4*)(B + (size_t)lr * NH + bn + (lq + i * 8) * 4);
    }
    // ---- store iter 0 ----
    {
        float2* dA = As; float2* dB = Bs;
#pragma unroll
        for (int i = 0; i < 4; i++) {
            int row = lr + i * 32;
            float va[4] = {pa[i].x, pa[i].y, pa[i].z, pa[i].w};
            float vb[4] = {pb[i].x, pb[i].y, pb[i].z, pb[i].w};
#pragma unroll
            for (int e = 0; e < 4; e++) {
                dA[(lq * 4 + e) * TSTR + row] = split2(va[e]);
                dB[lr * TSTR + (lq + i * 8) * 4 + e] = split2(vb[e]);
            }
        }
    }
    __syncthreads();

    for (int it = 0; it < nit; it++) {
        const int buf = it & 1;
        // prefetch next tile (global -> regs)
        if (it + 1 < nit) {
            const int k0 = (it + 1) * 32;
#pragma unroll
            for (int i = 0; i < 4; i++) {
                int gm = bm + lr + i * 32;
                pa[i] = (gm < M) ? *(const float4*)(A + (size_t)gm * K + k0 + lq * 4)
                                 : make_float4(0.f, 0.f, 0.f, 0.f);
                pb[i] = *(const float4*)(B + (size_t)(k0 + lr) * NH + bn + (lq + i * 8) * 4);
            }
        }
        // compute on current buffer
        {
            const float2* Ab = As + buf * SAS;
            const float2* Bb = Bs + buf * SAS;
#pragma unroll
            for (int ks = 0; ks < 4; ks++) {
                const int kb = ks * 8;
                uint32_t ah[4][4], al[4][4], bh[4][2], bl[4][2];
#pragma unroll
                for (int mt = 0; mt < 4; mt++) {
                    int m0 = wm * 64 + mt * 16 + g;
                    float2 v00 = Ab[(kb + lc) * TSTR + m0];
                    float2 v10 = Ab[(kb + lc) * TSTR + m0 + 8];
                    float2 v01 = Ab[(kb + lc + 4) * TSTR + m0];
                    float2 v11 = Ab[(kb + lc + 4) * TSTR + m0 + 8];
                    ah[mt][0] = __float_as_uint(v00.x); al[mt][0] = __float_as_uint(v00.y);
                    ah[mt][1] = __float_as_uint(v10.x); al[mt][1] = __float_as_uint(v10.y);
                    ah[mt][2] = __float_as_uint(v01.x); al[mt][2] = __float_as_uint(v01.y);
                    ah[mt][3] = __float_as_uint(v11.x); al[mt][3] = __float_as_uint(v11.y);
                }
#pragma unroll
                for (int nt = 0; nt < 4; nt++) {
                    int n0 = wn * 32 + nt * 8 + g;
                    float2 b0 = Bb[(kb + lc) * TSTR + n0];
                    float2 b1 = Bb[(kb + lc + 4) * TSTR + n0];
                    bh[nt][0] = __float_as_uint(b0.x); bl[nt][0] = __float_as_uint(b0.y);
                    bh[nt][1] = __float_as_uint(b1.x); bl[nt][1] = __float_as_uint(b1.y);
                }
#pragma unroll
                for (int mt = 0; mt < 4; mt++)
#pragma unroll
                    for (int nt = 0; nt < 4; nt++) {
                        mma_tf32(c[mt][nt], ah[mt], bh[nt]);
                        mma_tf32(c[mt][nt], ah[mt], bl[nt]);
                        mma_tf32(c[mt][nt], al[mt], bh[nt]);
                    }
            }
        }
        // store next tile into other buffer
        if (it + 1 < nit) {
            float2* dA = As + (buf ^ 1) * SAS;
            float2* dB = Bs + (buf ^ 1) * SAS;
#pragma unroll
            for (int i = 0; i < 4; i++) {
                int row = lr + i * 32;
                float va[4] = {pa[i].x, pa[i].y, pa[i].z, pa[i].w};
                float vb[4] = {pb[i].x, pb[i].y, pb[i].z, pb[i].w};
#pragma unroll
                for (int e = 0; e < 4; e++) {
                    dA[(lq * 4 + e) * TSTR + row] = split2(va[e]);
                    dB[lr * TSTR + (lq + i * 8) * 4 + e] = split2(vb[e]);
                }
            }
            __syncthreads();
        }
    }

    // ---- epilogue ----
    const float om_theta = 1.f - theta;
#pragma unroll
    for (int mt = 0; mt < 4; mt++) {
#pragma unroll
        for (int half = 0; half < 2; half++) {
            int row = bm + wm * 64 + mt * 16 + g + half * 8;
            if (row >= M) continue;
#pragma unroll
            for (int nt = 0; nt < 4; nt++) {
                int col = bn + wn * 32 + nt * 8 + 2 * lc;
                size_t off = (size_t)row * NH + col;
                float vx = c[mt][nt][2 * half];
                float vy = c[mt][nt][2 * half + 1];
                if (mode == 0) {
                    vx += bias[col];     vy += bias[col + 1];
                    vx = vx > 0.f ? vx : 0.f;
                    vy = vy > 0.f ? vy : 0.f;
                    *(float2*)(C + off)  = make_float2(vx, vy);
                    *(float2*)(C2 + off) = make_float2(vx, vy);
                } else {
                    float2 r = *(const float2*)(R + off);
                    vx = theta * vx + om_theta * r.x;
                    vy = theta * vy + om_theta * r.y;
                    vx = vx > 0.f ? vx : 0.f;
                    vy = vy > 0.f ? vy : 0.f;
                    *(float2*)(C + off) = make_float2(vx, vy);
                }
            }
        }
    }
}

// ---------------- CSR build ----------------
__global__ void k_zero() {
    int i = blockIdx.x * 256 + threadIdx.x;
    if (i < NNODES) g_cnt[i] = 0;
}
__global__ void k_hist(const int* __restrict__ edst) {
    int i = blockIdx.x * 256 + threadIdx.x;
    if (i < NEDGES) atomicAdd(&g_cnt[edst[i]], 1);
}
__global__ void k_scan1() {
    __shared__ int s[1024];
    int i = blockIdx.x * 1024 + threadIdx.x;
    int v = (i < NNODES) ? g_cnt[i] : 0;
    s[threadIdx.x] = v;
    __syncthreads();
    for (int off = 1; off < 1024; off <<= 1) {
        int t = 0;
        if (threadIdx.x >= off) t = s[threadIdx.x - off];
        __syncthreads();
        if (threadIdx.x >= off) s[threadIdx.x] += t;
        __syncthreads();
    }
    if (i < NNODES) g_excl[i] = s[threadIdx.x] - v;
    if (threadIdx.x == 1023) g_bsum[blockIdx.x] = s[1023];
}
__global__ void k_scan2(int nb) {
    if (threadIdx.x == 0) {
        int run = 0;
        for (int i = 0; i < nb; i++) { int t = g_bsum[i]; g_bsum[i] = run; run += t; }
    }
}
__global__ void k_scan3() {
    int i = blockIdx.x * 1024 + threadIdx.x;
    if (i < NNODES) {
        int v = g_excl[i] + g_bsum[i >> 10];
        g_rowptr[i] = v;
        g_cursor[i] = v;
    }
    if (i == 0) g_rowptr[NNODES] = NEDGES;
}
__global__ void k_scatter(const int* __restrict__ esrc, const int* __restrict__ edst,
                          const float* __restrict__ ew) {
    int i = blockIdx.x * 256 + threadIdx.x;
    if (i < NEDGES) {
        int d = edst[i];
        int pos = atomicAdd(&g_cursor[d], 1);
        g_col[pos] = esrc[i];
        g_wt[pos]  = ew[i];
    }
}

// ---------------- SpMM + support fusion (feature-chunked for L2 residency) ----------------
// pass over 128-feature half `chunk`: sup[:,c] = 0.9 * (A_sp @ h[:,c]) + 0.1 * h0[:,c]
// 32 lanes per node (one warp), 8 nodes per block. Gathers are 512B contiguous
// per row-half; working set per pass = 51 MB -> L2-resident.
__global__ void __launch_bounds__(256) k_spmm_half(int chunk) {
    const int node = blockIdx.x * 8 + (threadIdx.x >> 5);
    const int lane = threadIdx.x & 31;
    const int rs = g_rowptr[node];
    const int re = g_rowptr[node + 1];
    const float4* hb = (const float4*)g_h + chunk * 32 + lane;   // + s*64 per row
    float ax = 0.f, ay = 0.f, az = 0.f, aw = 0.f;
    int p = rs;
    for (; p + 4 <= re; p += 4) {
        int s0 = __ldg(&g_col[p]);
        int s1 = __ldg(&g_col[p + 1]);
        int s2 = __ldg(&g_col[p + 2]);
        int s3 = __ldg(&g_col[p + 3]);
        float w0 = __ldg(&g_wt[p]);
        float w1 = __ldg(&g_wt[p + 1]);
        float w2 = __ldg(&g_wt[p + 2]);
        float w3 = __ldg(&g_wt[p + 3]);
        float4 v0 = __ldg(hb + (size_t)s0 * 64);
        float4 v1 = __ldg(hb + (size_t)s1 * 64);
        float4 v2 = __ldg(hb + (size_t)s2 * 64);
        float4 v3 = __ldg(hb + (size_t)s3 * 64);
        ax = fmaf(w0, v0.x, ax); ay = fmaf(w0, v0.y, ay);
        az = fmaf(w0, v0.z, az); aw = fmaf(w0, v0.w, aw);
        ax = fmaf(w1, v1.x, ax); ay = fmaf(w1, v1.y, ay);
        az = fmaf(w1, v1.z, az); aw = fmaf(w1, v1.w, aw);
        ax = fmaf(w2, v2.x, ax); ay = fmaf(w2, v2.y, ay);
        az = fmaf(w2, v2.z, az); aw = fmaf(w2, v2.w, aw);
        ax = fmaf(w3, v3.x, ax); ay = fmaf(w3, v3.y, ay);
        az = fmaf(w3, v3.z, az); aw = fmaf(w3, v3.w, aw);
    }
    for (; p < re; p++) {
        int s0 = __ldg(&g_col[p]);
        float w0 = __ldg(&g_wt[p]);
        float4 v0 = __ldg(hb + (size_t)s0 * 64);
        ax = fmaf(w0, v0.x, ax); ay = fmaf(w0, v0.y, ay);
        az = fmaf(w0, v0.z, az); aw = fmaf(w0, v0.w, aw);
    }
    const size_t off = (size_t)node * 64 + chunk * 32 + lane;
    float4 r = __ldg((const float4*)g_h0 + off);
    float4 o;
    o.x = 0.9f * ax + ALPHA * r.x;
    o.y = 0.9f * ay + ALPHA * r.y;
    o.z = 0.9f * az + ALPHA * r.z;
    o.w = 0.9f * aw + ALPHA * r.w;
    ((float4*)g_sup)[off] = o;
}

// ---------------- classifier + log_softmax ----------------
__global__ void __launch_bounds__(320) k_classifier(const float* __restrict__ W1,
                                                    const float* __restrict__ b1,
                                                    float* __restrict__ out) {
    __shared__ float W1s[NCLS * 257];
    __shared__ float logits[8][41];
    __shared__ float mx[8], lse[8];
    const int tid = threadIdx.x;
    for (int idx = tid; idx < NCLS * NH; idx += 320) {
        int c = idx >> 8, k = idx & 255;
        W1s[c * 257 + k] = W1[idx];
    }
    __syncthreads();
    const int ln = tid / NCLS;
    const int c  = tid % NCLS;
    const int node = blockIdx.x * 8 + ln;
    const float* hrow = g_h + (size_t)node * NH;
    float acc = __ldg(&b1[c]);
#pragma unroll 4
    for (int k = 0; k < NH; k++)
        acc = fmaf(__ldg(hrow + k), W1s[c * 257 + k], acc);
    logits[ln][c] = acc;
    __syncthreads();
    if (tid < 8) {
        float m = -1e30f;
        for (int j = 0; j < NCLS; j++) m = fmaxf(m, logits[tid][j]);
        float s = 0.f;
        for (int j = 0; j < NCLS; j++) s += expf(logits[tid][j] - m);
        mx[tid] = m;
        lse[tid] = logf(s);
    }
    __syncthreads();
    out[(size_t)node * NCLS + c] = logits[ln][c] - mx[ln] - lse[ln];
}

// ---------------- launch ----------------
extern "C" void kernel_launch(void* const* d_in, const int* in_sizes, int n_in,
                              void* d_out, int out_size) {
    const float* x     = (const float*)d_in[0];
    const int*   esrc  = (const int*)d_in[1];
    const int*   edst  = (const int*)d_in[2];
    const float* ew    = (const float*)d_in[3];
    const float* W0    = (const float*)d_in[4];
    const float* b0    = (const float*)d_in[5];
    const float* convW = (const float*)d_in[6];
    const float* W1    = (const float*)d_in[7];
    const float* b1    = (const float*)d_in[8];
    float* out = (float*)d_out;

    float *pB, *pB2, *pB3, *pS, *pW0T, *ph, *ph0, *psup, *ptW;
    cudaGetSymbolAddress((void**)&pB,   g_Bmat);
    cudaGetSymbolAddress((void**)&pB2,  g_B2);
    cudaGetSymbolAddress((void**)&pB3,  g_B3);
    cudaGetSymbolAddress((void**)&pS,   g_S);
    cudaGetSymbolAddress((void**)&pW0T, g_W0T);
    cudaGetSymbolAddress((void**)&ph,   g_h);
    cudaGetSymbolAddress((void**)&ph0,  g_h0);
    cudaGetSymbolAddress((void**)&psup, g_sup);
    cudaGetSymbolAddress((void**)&ptW,  g_tW);

    const int SMEM_TC = 4 * SAS * (int)sizeof(float2);   // 136,192 B
    cudaFuncSetAttribute(k_gemm_tc, cudaFuncAttributeMaxDynamicSharedMemorySize, SMEM_TC);

    // ---- orthogonalization of all 9 weight matrices (batched) ----
    k_center0<<<NH, 256>>>(W0);
    k_centerL<<<NLAY * NH, 256>>>(convW);
    k_cov<<<dim3(4, 4, NB), 256>>>();
    k_norm<<<NB, 256>>>();
    k_scaleinit<<<(NB * NH * NH) / 256, 256>>>();
    for (int it = 0; it < 5; it++) {
        k_ns<0><<<dim3(4, 4, NB), 256>>>(pB,  pB, pB2);   // B2 = B@B
        k_ns<0><<<dim3(4, 4, NB), 256>>>(pB2, pB, pB3);   // B3 = B2@B
        k_ns<1><<<dim3(4, 4, NB), 256>>>(pB3, pS, pB);    // B = 1.5B - 0.5*B3@S
    }
    k_wfinal<<<dim3(4, 8, NB), 256>>>();
    k_transpose<<<(NF * NH) / 256, 256>>>();

    // ---- input projection: h = relu(x @ W0o^T + b0), h0 = h ----
    const int MT = (NNODES + 127) / 128;
    k_gemm_tc<<<dim3(MT, 2), 256, SMEM_TC>>>(x, pW0T, ph, ph0, b0, nullptr,
                                             NNODES, NF, 0.f, 0);

    // ---- CSR build (dst-sorted) ----
    k_zero<<<(NNODES + 255) / 256, 256>>>();
    k_hist<<<(NEDGES + 255) / 256, 256>>>(edst);
    const int NBLK = (NNODES + 1023) / 1024;
    k_scan1<<<NBLK, 1024>>>();
    k_scan2<<<1, 32>>>(NBLK);
    k_scan3<<<NBLK, 1024>>>();
    k_scatter<<<(NEDGES + 255) / 256, 256>>>(esrc, edst, ew);

    // ---- 8 GCNII layers ----
    for (int l = 1; l <= NLAY; l++) {
        float theta = logf(0.5f / (float)l + 1.f);
        k_spmm_half<<<NNODES / 8, 256>>>(0);
        k_spmm_half<<<NNODES / 8, 256>>>(1);
        k_gemm_tc<<<dim3(MT, 2), 256, SMEM_TC>>>(psup, ptW + (size_t)(l - 1) * NH * NH,
                                                 ph, nullptr, nullptr, psup,
                                                 NNODES, NH, theta, 1);
    }

    // ---- classifier + log_softmax ----
    k_classifier<<<NNODES / 8, 320>>>(W1, b1, out);
}